// round 14
// baseline (speedup 1.0000x reference)
#include <cuda_runtime.h>
#include <cstdint>

#define BATCH   256
#define TSTEPS  1000
#define LIN     30
#define NCH     16
#define KW      7
#define LO      24
#define JDIM    384      // NCH*LO
#define NOUT    35
#define GR      12       // j-groups per output
#define JT      32       // j's per FC thread
#define NTHREADS 448     // warps 0-11: A + B(r=wid,o=lane) | w12+w13l0-3: B-extra | w13: C | w12 l29-31: C-extra
#define CHUNK   40       // timesteps per smem chunk (20 regions, even)
#define NCHUNK  (TSTEPS / CHUNK)
#define NREG    (CHUNK / 2)
#define ROWP    32       // padded x row stride (floats) -> one 128B line per row
#define SPKG    36       // spike group stride (floats)
#define PCOL    37       // part row stride (odd words -> conflict-free C reads)

typedef unsigned long long ull;

__device__ __forceinline__ uint32_t smem_u32(const void* p) {
    return (uint32_t)__cvta_generic_to_shared(p);
}
__device__ __forceinline__ void cp_async8(uint32_t dst, const void* src) {
    asm volatile("cp.async.ca.shared.global [%0], [%1], 8;" :: "r"(dst), "l"(src));
}
__device__ __forceinline__ void cp_commit() { asm volatile("cp.async.commit_group;"); }
__device__ __forceinline__ void cp_wait1()  { asm volatile("cp.async.wait_group 1;" ::: "memory"); }
__device__ __forceinline__ void cp_wait0()  { asm volatile("cp.async.wait_group 0;" ::: "memory"); }

__device__ __forceinline__ ull pk(float a, float b) {
    ull r; asm("mov.b64 %0, {%1,%2};" : "=l"(r) : "f"(a), "f"(b)); return r;
}
__device__ __forceinline__ void upk(ull v, float& a, float& b) {
    asm("mov.b64 {%0,%1}, %2;" : "=f"(a), "=f"(b) : "l"(v));
}
__device__ __forceinline__ ull f2fma(ull a, ull b, ull c) {
    ull d; asm("fma.rn.f32x2 %0, %1, %2, %3;" : "=l"(d) : "l"(a), "l"(b), "l"(c)); return d;
}

#define SPK_PS (12 * SPKG * 4)   // spk [parity][substep] plane stride in bytes

// ---- sub-phase helpers (arithmetic sequences verbatim from the 485us kernel) ----

#define DO_C_SUB(PBUF, SSUB)                                                   \
  {                                                                            \
    float c2 = part[PBUF][SSUB][0][ccol];                                      \
    _Pragma("unroll")                                                          \
    for (int rr2 = 1; rr2 < GR; ++rr2) c2 += part[PBUF][SSUB][rr2][ccol];      \
    c2 = __fadd_rn(c2, bias2);                                                 \
    float r2 = (mem2 > 1.0f) ? 1.0f : 0.0f;                                    \
    mem2 = __fsub_rn(__fadd_rn(__fmul_rn(0.9f, mem2), c2), r2);                \
    acc += (double)mem2;                                                       \
  }

#define DO_B_SUB(PBUF, SSUB)                                                   \
  {                                                                            \
    uint32_t sp = spkAddr + (uint32_t)((2 * (PBUF) + (SSUB)) * SPK_PS);        \
    ull a0 = 0ull, a1 = 0ull;                                                  \
    _Pragma("unroll")                                                          \
    for (int k = 0; k < JT / 2; k += 2) {                                      \
      ull s0, s1;                                                              \
      asm("ld.shared.v2.u64 {%0,%1}, [%2];"                                    \
          : "=l"(s0), "=l"(s1) : "r"(sp + (uint32_t)(k * 8)));                 \
      a0 = f2fma(s0, w2[k],     a0);                                           \
      a1 = f2fma(s1, w2[k + 1], a1);                                           \
    }                                                                          \
    float x0_, x1_, y0_, y1_;                                                  \
    upk(a0, x0_, x1_);                                                         \
    upk(a1, y0_, y1_);                                                         \
    part[(PBUF) ^ 1][SSUB][brow][bcol] = (x0_ + x1_) + (y0_ + y1_);            \
  }

#define DO_A_SUB(PBUF, SSUB, XROW)                                             \
  {                                                                            \
    const float* xr = (XROW) + pos;                                            \
    float s = __fmul_rn(xr[0], wc[0]);                                         \
    _Pragma("unroll")                                                          \
    for (int k = 1; k < KW; ++k) s = __fmaf_rn(xr[k], wc[k], s);               \
    float c1 = __fadd_rn(s, bc);                                               \
    float r1 = (mem1 > 1.0f) ? 1.0f : 0.0f;                                    \
    mem1 = __fsub_rn(__fadd_rn(__fmul_rn(0.9f, mem1), c1), r1);                \
    spk[PBUF][SSUB][aSlot] = (mem1 > 1.0f) ? 1.0f : 0.0f;                      \
  }

// One region = 2 timesteps: C(2R-4),C(2R-3); B(2R-2),B(2R-1); A(2R),A(2R+1).
// pr = R&1. A writes spk[pr][*]; B reads spk[pr^1][*], writes part[pr][*];
// C reads part[pr^1][*].
#define REGION(PR, XR0, XR1, DOA, DOB, DOC)                                    \
  {                                                                            \
    if ((DOC) && cTh) {                                                        \
      DO_C_SUB((PR) ^ 1, 0)                                                    \
      DO_C_SUB((PR) ^ 1, 1)                                                    \
    }                                                                          \
    if ((DOB) && bTh) {                                                        \
      DO_B_SUB((PR) ^ 1, 0)                                                    \
      DO_B_SUB((PR) ^ 1, 1)                                                    \
    }                                                                          \
    if ((DOA) && aTh) {                                                        \
      DO_A_SUB((PR), 0, XR0)                                                   \
      DO_A_SUB((PR), 1, XR1)                                                   \
    }                                                                          \
    __syncthreads();                                                           \
  }

__global__ __launch_bounds__(NTHREADS, 2)
void snn_kernel(const float* __restrict__ x,
                const float* __restrict__ conv_w,
                const float* __restrict__ conv_b,
                const float* __restrict__ fc_w,
                const float* __restrict__ fc_b,
                float* __restrict__ out)
{
    __shared__ __align__(128) float xs[2][CHUNK * ROWP];    // 10.24 KB, aligned rows
    __shared__ __align__(16)  float spk[2][2][12 * SPKG];   // [parity][substep], group stride 36
    __shared__ float part[2][2][GR][PCOL];                  // [parity][substep], row stride 37

    const int b    = blockIdx.x;
    const int tid  = threadIdx.x;
    const int wid  = tid >> 5;
    const int lane = tid & 31;

    // ---- Phase A state (warps 0-11): thread owns j=tid (ch=j/24, pos=j%24) ----
    const bool aTh   = (wid < 12);
    const int  pos   = tid % LO;
    const int  aSlot = wid * SPKG + lane;    // group j>>5, ascending offset j&31
    float wc[KW], bc = 0.f, mem1 = 0.f;
    if (aTh) {
        const int ch = tid / LO;
        #pragma unroll
        for (int k = 0; k < KW; ++k) wc[k] = conv_w[ch * KW + k];
        bc = conv_b[ch];
    }

    // ---- Phase B state: warps 0-11 -> (r=wid, o=lane); threads 384-419 -> (r=i/3, o=32+i%3) ----
    bool bTh = false;
    int  brow = 0, bcol = 0;
    if (wid < 12)            { bTh = true; brow = wid;              bcol = lane;         }
    else if (tid < 384 + 36) { bTh = true; int i = tid - 384; brow = i / 3; bcol = 32 + i % 3; }
    ull w2[JT / 2];
    if (bTh) {
        #pragma unroll
        for (int k = 0; k < JT / 2; ++k)
            w2[k] = pk(fc_w[bcol * JDIM + brow * JT + 2 * k],
                       fc_w[bcol * JDIM + brow * JT + 2 * k + 1]);
    }
    const uint32_t spkAddr = smem_u32(&spk[0][0][0]) + (uint32_t)(brow * SPKG * 4);

    // ---- Phase C state: warp 13 -> outputs 0-31; warp 12 lanes 29-31 -> 32-34 ----
    bool cTh = false;
    int  ccol = 0;
    if (wid == 13)                    { cTh = true; ccol = lane;            }
    else if (wid == 12 && lane >= 29) { cTh = true; ccol = 32 + (lane - 29); }
    float  bias2 = 0.f, mem2 = 0.f;
    double acc   = 0.0;
    if (cTh) bias2 = fc_b[ccol];

    const float* xb = x + (size_t)b * TSTEPS * LIN;

    // ---- prefetch chunk 0 into padded rows (600 8B units over 448 threads) ----
    {
        uint32_t sbase = smem_u32(&xs[0][0]);
        for (int i = tid; i < CHUNK * 15; i += NTHREADS) {
            int t = i / 15, c = i - t * 15;
            cp_async8(sbase + (uint32_t)(t * ROWP * 4 + c * 8), xb + t * LIN + c * 2);
        }
        cp_commit();
    }

    for (int chunk = 0; chunk < NCHUNK; ++chunk) {
        const int buf = chunk & 1;
        if (chunk + 1 < NCHUNK) {
            uint32_t sbase   = smem_u32(&xs[buf ^ 1][0]);
            const float* src = xb + (size_t)(chunk + 1) * CHUNK * LIN;
            for (int i = tid; i < CHUNK * 15; i += NTHREADS) {
                int t = i / 15, c = i - t * 15;
                cp_async8(sbase + (uint32_t)(t * ROWP * 4 + c * 8), src + t * LIN + c * 2);
            }
            cp_commit();
            cp_wait1();
        } else {
            cp_wait0();
        }
        __syncthreads();

        const float* xbase = &xs[buf][0];
        if (chunk == 0) {
            // fill: region 0 = A only; region 1 = A+B; region >=2 = all
            #pragma unroll 2
            for (int rr = 0; rr < NREG; ++rr)
                REGION(rr & 1, xbase + 2 * rr * ROWP, xbase + (2 * rr + 1) * ROWP,
                       true, rr >= 1, rr >= 2);
        } else {
            // steady state (NREG even -> region parity = rr&1 every chunk)
            #pragma unroll 2
            for (int rr = 0; rr < NREG; ++rr)
                REGION(rr & 1, xbase + 2 * rr * ROWP, xbase + (2 * rr + 1) * ROWP,
                       true, true, true);
        }
    }

    // ---- drain: region 500 (pr=0): B(998,999), C(996,997); region 501: C(998,999) ----
    REGION(0, (const float*)nullptr, (const float*)nullptr, false, true, true);
    REGION(1, (const float*)nullptr, (const float*)nullptr, false, false, true);

    if (cTh)
        out[b * NOUT + ccol] = (float)(acc * (1.0 / (double)TSTEPS));
}

extern "C" void kernel_launch(void* const* d_in, const int* in_sizes, int n_in,
                              void* d_out, int out_size)
{
    const float* x      = (const float*)d_in[0];
    const float* conv_w = (const float*)d_in[1];
    const float* conv_b = (const float*)d_in[2];
    const float* fc_w   = (const float*)d_in[3];
    const float* fc_b   = (const float*)d_in[4];
    snn_kernel<<<BATCH, NTHREADS>>>(x, conv_w, conv_b, fc_w, fc_b, (float*)d_out);
}

// round 16
// speedup vs baseline: 1.4229x; 1.4229x over previous
#include <cuda_runtime.h>
#include <cstdint>

#define BATCH   256
#define TSTEPS  1000
#define LIN     30
#define NCH     16
#define KW      7
#define LO      24
#define JDIM    384      // NCH*LO
#define NOUT    35
#define OPAD    36       // padded outputs
#define GR      12       // j-groups per output
#define JT      32       // j's per FC thread
#define NTHREADS 448
#define CHUNK   40       // timesteps per smem chunk (20 regions, even)
#define NCHUNK  (TSTEPS / CHUNK)
#define NREG    (CHUNK / 2)

typedef unsigned long long ull;

__device__ __forceinline__ uint32_t smem_u32(const void* p) {
    return (uint32_t)__cvta_generic_to_shared(p);
}
__device__ __forceinline__ void cp_async8(uint32_t dst, const void* src) {
    asm volatile("cp.async.ca.shared.global [%0], [%1], 8;" :: "r"(dst), "l"(src));
}
__device__ __forceinline__ void cp_commit() { asm volatile("cp.async.commit_group;"); }
__device__ __forceinline__ void cp_wait1()  { asm volatile("cp.async.wait_group 1;" ::: "memory"); }
__device__ __forceinline__ void cp_wait0()  { asm volatile("cp.async.wait_group 0;" ::: "memory"); }

__device__ __forceinline__ ull pk(float a, float b) {
    ull r; asm("mov.b64 %0, {%1,%2};" : "=l"(r) : "f"(a), "f"(b)); return r;
}
__device__ __forceinline__ void upk(ull v, float& a, float& b) {
    asm("mov.b64 {%0,%1}, %2;" : "=f"(a), "=f"(b) : "l"(v));
}
__device__ __forceinline__ ull f2fma(ull a, ull b, ull c) {
    ull d; asm("fma.rn.f32x2 %0, %1, %2, %3;" : "=l"(d) : "l"(a), "l"(b), "l"(c)); return d;
}
// Expand u32 holding two bf16 spikes {hi:spk(2k+1), lo:spk(2k)} into f32x2
// {lo<<16, hi&0xFFFF0000}. Exact: bf16 0/1 -> f32 0/1.
__device__ __forceinline__ ull bexp(uint32_t v) {
    ull d;
    asm("{\n\t"
        ".reg .b32 lo, hi;\n\t"
        "shl.b32 lo, %1, 16;\n\t"
        "and.b32 hi, %1, 0xFFFF0000;\n\t"
        "mov.b64 %0, {lo, hi};\n\t"
        "}" : "=l"(d) : "r"(v));
    return d;
}

#define SPK_PS (JDIM * 2)   // spk [parity][substep] plane stride in bytes (u16)

// ---- sub-phase helpers (arithmetic sequences verbatim from the 485us kernel) ----

#define DO_C_SUB(PBUF, SSUB)                                                   \
  {                                                                            \
    float c2 = part[PBUF][SSUB][0][cIdx];                                      \
    _Pragma("unroll")                                                          \
    for (int rr2 = 1; rr2 < GR; ++rr2) c2 += part[PBUF][SSUB][rr2][cIdx];      \
    c2 = __fadd_rn(c2, bias2);                                                 \
    float r2 = (mem2 > 1.0f) ? 1.0f : 0.0f;                                    \
    mem2 = __fsub_rn(__fadd_rn(__fmul_rn(0.9f, mem2), c2), r2);                \
    acc += (double)mem2;                                                       \
  }

#define DO_B_SUB(PBUF, SSUB)                                                   \
  {                                                                            \
    uint32_t sp = spkAddr + (uint32_t)((2 * (PBUF) + (SSUB)) * SPK_PS);        \
    ull a0 = 0ull, a1 = 0ull;                                                  \
    _Pragma("unroll")                                                          \
    for (int q = 0; q < 4; ++q) {                                              \
      uint32_t v0, v1, v2, v3;                                                 \
      asm("ld.shared.v4.u32 {%0,%1,%2,%3}, [%4];"                              \
          : "=r"(v0), "=r"(v1), "=r"(v2), "=r"(v3)                             \
          : "r"(sp + (uint32_t)(q * 16)));                                     \
      a0 = f2fma(bexp(v0), w2[4 * q],     a0);                                 \
      a1 = f2fma(bexp(v1), w2[4 * q + 1], a1);                                 \
      a0 = f2fma(bexp(v2), w2[4 * q + 2], a0);                                 \
      a1 = f2fma(bexp(v3), w2[4 * q + 3], a1);                                 \
    }                                                                          \
    float x0_, x1_, y0_, y1_;                                                  \
    upk(a0, x0_, x1_);                                                         \
    upk(a1, y0_, y1_);                                                         \
    part[(PBUF) ^ 1][SSUB][r][o] = (x0_ + x1_) + (y0_ + y1_);                  \
  }

#define DO_A_SUB(PBUF, SSUB, XROW)                                             \
  {                                                                            \
    const float* xr = (XROW) + pos;                                            \
    float s = __fmul_rn(xr[0], wc[0]);                                         \
    _Pragma("unroll")                                                          \
    for (int k = 1; k < KW; ++k) s = __fmaf_rn(xr[k], wc[k], s);               \
    float c1 = __fadd_rn(s, bc);                                               \
    float r1 = (mem1 > 1.0f) ? 1.0f : 0.0f;                                    \
    mem1 = __fsub_rn(__fadd_rn(__fmul_rn(0.9f, mem1), c1), r1);                \
    spk[PBUF][SSUB][tid] = (mem1 > 1.0f) ? (uint16_t)0x3F80 : (uint16_t)0;     \
  }

// One region = 2 timesteps: C(2R-4),C(2R-3); B(2R-2),B(2R-1); A(2R),A(2R+1).
// pr = R&1. A writes spk[pr][*]; B reads spk[pr^1][*], writes part[pr][*];
// C reads part[pr^1][*].
#define REGION(PR, XR0, XR1, DOA, DOB, DOC)                                    \
  {                                                                            \
    if ((DOC) && cTh) {                                                        \
      DO_C_SUB((PR) ^ 1, 0)                                                    \
      DO_C_SUB((PR) ^ 1, 1)                                                    \
    }                                                                          \
    if ((DOB) && fcth) {                                                       \
      DO_B_SUB((PR) ^ 1, 0)                                                    \
      DO_B_SUB((PR) ^ 1, 1)                                                    \
    }                                                                          \
    if ((DOA) && tid < JDIM) {                                                 \
      DO_A_SUB((PR), 0, XR0)                                                   \
      DO_A_SUB((PR), 1, XR1)                                                   \
    }                                                                          \
    __syncthreads();                                                           \
  }

__global__ __launch_bounds__(NTHREADS, 2)
void snn_kernel(const float* __restrict__ x,
                const float* __restrict__ conv_w,
                const float* __restrict__ conv_b,
                const float* __restrict__ fc_w,
                const float* __restrict__ fc_b,
                float* __restrict__ out)
{
    __shared__ __align__(16) float    xs[2][CHUNK * LIN];   // 9.6 KB double-buffered x
    __shared__ __align__(16) uint16_t spk[2][2][JDIM];      // [parity][substep] bf16 spikes
    __shared__ float part[2][2][GR][40];                    // [parity][substep]

    const int b   = blockIdx.x;
    const int tid = threadIdx.x;

    // ---- Phase A state: thread tid < 384 owns mem1[tid], tid = ch*24 + pos ----
    float wc[KW];
    float bc = 0.f, mem1 = 0.f;
    int pos = 0;
    if (tid < JDIM) {
        int ch = tid / LO;
        pos    = tid % LO;
        #pragma unroll
        for (int k = 0; k < KW; ++k) wc[k] = conv_w[ch * KW + k];
        bc = conv_b[ch];
    }

    // ---- Phase B state: threads 0-431 -> output o = tid%36, group r = tid/36 ----
    const bool fcth = (tid < GR * OPAD);
    const int  o    = tid % OPAD;
    const int  r    = tid / OPAD;
    ull w2[JT / 2];
    if (fcth) {
        #pragma unroll
        for (int k = 0; k < JT / 2; ++k) {
            float lo_ = 0.f, hi_ = 0.f;
            if (o < NOUT) {
                lo_ = fc_w[o * JDIM + r * JT + 2 * k];
                hi_ = fc_w[o * JDIM + r * JT + 2 * k + 1];
            }
            w2[k] = pk(lo_, hi_);
        }
    }
    const uint32_t spkAddr = smem_u32(&spk[0][0][0]) + (uint32_t)(r * JT * 2);

    // ---- Phase C state: threads 384..418 own output cIdx (warp 12) ----
    const bool cTh  = (tid >= JDIM) && (tid < JDIM + NOUT);
    const int  cIdx = tid - JDIM;
    float  bias2 = 0.f, mem2 = 0.f;
    double acc   = 0.0;
    if (cTh) bias2 = fc_b[cIdx];

    const float* xb = x + (size_t)b * TSTEPS * LIN;

    // ---- prefetch chunk 0 (1200 floats = 600 x 8B) ----
    {
        uint32_t sbase = smem_u32(&xs[0][0]);
        for (int i = tid; i < CHUNK * LIN / 2; i += NTHREADS)
            cp_async8(sbase + i * 8, xb + i * 2);
        cp_commit();
    }

    for (int chunk = 0; chunk < NCHUNK; ++chunk) {
        const int buf = chunk & 1;
        if (chunk + 1 < NCHUNK) {
            uint32_t sbase   = smem_u32(&xs[buf ^ 1][0]);
            const float* src = xb + (size_t)(chunk + 1) * CHUNK * LIN;
            for (int i = tid; i < CHUNK * LIN / 2; i += NTHREADS)
                cp_async8(sbase + i * 8, src + i * 2);
            cp_commit();
            cp_wait1();
        } else {
            cp_wait0();
        }
        __syncthreads();

        const float* xrow = &xs[buf][0];
        if (chunk == 0) {
            // fill: region 0 = A only; region 1 = A+B; region >=2 = all
            #pragma unroll 2
            for (int rr = 0; rr < NREG; ++rr)
                REGION(rr & 1, xrow + 2 * rr * LIN, xrow + (2 * rr + 1) * LIN,
                       true, rr >= 1, rr >= 2);
        } else {
            // steady state (NREG even -> region parity = rr&1 every chunk)
            #pragma unroll 2
            for (int rr = 0; rr < NREG; ++rr)
                REGION(rr & 1, xrow + 2 * rr * LIN, xrow + (2 * rr + 1) * LIN,
                       true, true, true);
        }
    }

    // ---- drain: region 500 (pr=0): B(998,999), C(996,997); region 501: C(998,999) ----
    REGION(0, (const float*)nullptr, (const float*)nullptr, false, true, true);
    REGION(1, (const float*)nullptr, (const float*)nullptr, false, false, true);

    if (cTh)
        out[b * NOUT + cIdx] = (float)(acc * (1.0 / (double)TSTEPS));
}

extern "C" void kernel_launch(void* const* d_in, const int* in_sizes, int n_in,
                              void* d_out, int out_size)
{
    const float* x      = (const float*)d_in[0];
    const float* conv_w = (const float*)d_in[1];
    const float* conv_b = (const float*)d_in[2];
    const float* fc_w   = (const float*)d_in[3];
    const float* fc_b   = (const float*)d_in[4];
    snn_kernel<<<BATCH, NTHREADS>>>(x, conv_w, conv_b, fc_w, fc_b, (float*)d_out);
}